// round 12
// baseline (speedup 1.0000x reference)
#include <cuda_runtime.h>
#include <cuda_bf16.h>
#include <cstdint>
#include <math.h>

#define NPTS 8192
#define DIM  256
#define NCLS 10
#define KNN  3
#define NT   64
#define NTRI (NT*(NT+1)/2)
#define NTC  8
#define CTRI (NTC*(NTC+1)/2)
#define LCAP (1 << 20)
#define BMARGIN 0.1f

// ---------------- device scratch ----------------
__device__ float g_sq[NPTS];
__device__ float g_H[NPTS];
__device__ float g_L[NPTS];
__device__ int   g_cnt[NPTS];
__device__ float g_anchor[NPTS];
__device__ int   g_anchi[NPTS];
__device__ float4 g_top4[(size_t)NPTS * NTC];
__device__ int4   g_top4i[(size_t)NPTS * NTC];
__device__ double g_part[64];
__device__ __nv_bfloat16 g_Xhi[(size_t)NPTS * DIM];
__device__ __nv_bfloat16 g_Xlo[(size_t)NPTS * DIM];
__device__ int g_perm[NPTS];
__device__ int g_cbase[NCLS];
__device__ int g_ccnt[NCLS];
__device__ int g_nlist;
__device__ uint32_t g_list[LCAP];

// ---------------- helpers ----------------
__device__ __forceinline__ uint32_t smem_u32(const void* p) {
    uint32_t a;
    asm("{ .reg .u64 t; cvta.to.shared.u64 t, %1; cvt.u32.u64 %0, t; }" : "=r"(a) : "l"(p));
    return a;
}
__device__ __forceinline__ void cp16(uint32_t dst, const void* src) {
    asm volatile("cp.async.cg.shared.global [%0], [%1], 16;" :: "r"(dst), "l"(src));
}
#define CP_COMMIT() asm volatile("cp.async.commit_group;" ::: "memory")
#define CP_WAIT0()  asm volatile("cp.async.wait_group 0;" ::: "memory")

#define MMA16816(d, a, b) \
  asm volatile("mma.sync.aligned.m16n8k16.row.col.f32.bf16.bf16.f32 " \
      "{%0,%1,%2,%3}, {%4,%5,%6,%7}, {%8,%9}, {%0,%1,%2,%3};" \
      : "+f"(d[0]), "+f"(d[1]), "+f"(d[2]), "+f"(d[3]) \
      : "r"(a[0]), "r"(a[1]), "r"(a[2]), "r"(a[3]), "r"(b[0]), "r"(b[1]))

__device__ __forceinline__ void ldsm_x4(uint32_t* r, uint32_t addr) {
    asm volatile("ldmatrix.sync.aligned.m8n8.x4.shared.b16 {%0,%1,%2,%3}, [%4];"
        : "=r"(r[0]), "=r"(r[1]), "=r"(r[2]), "=r"(r[3]) : "r"(addr));
}

__device__ __forceinline__ void ins4i(float v, int id, float* b, int* bi) {
    if (v < b[3]) {
        if (v < b[2]) {
            b[3] = b[2]; bi[3] = bi[2];
            if (v < b[1]) {
                b[2] = b[1]; bi[2] = bi[1];
                if (v < b[0]) { b[1] = b[0]; bi[1] = bi[0]; b[0] = v; bi[0] = id; }
                else          { b[1] = v; bi[1] = id; }
            } else { b[2] = v; bi[2] = id; }
        } else { b[3] = v; bi[3] = id; }
    }
}
__device__ __forceinline__ void merge4i(float* a, int* ai, const float* b, const int* bi) {
    float rv[4]; int ri[4];
    int x = 0, y = 0;
    #pragma unroll
    for (int t = 0; t < 4; t++) {
        bool ta = (y >= 4) || (x < 4 && a[x] <= b[y]);
        if (ta) { rv[t] = a[x]; ri[t] = ai[x]; x++; }
        else    { rv[t] = b[y]; ri[t] = bi[y]; y++; }
    }
    #pragma unroll
    for (int t = 0; t < 4; t++) { a[t] = rv[t]; ai[t] = ri[t]; }
}
__device__ __forceinline__ float b_lo(uint32_t u) {
    return __bfloat162float(__ushort_as_bfloat16((unsigned short)(u & 0xffffu)));
}
__device__ __forceinline__ float b_hi(uint32_t u) {
    return __bfloat162float(__ushort_as_bfloat16((unsigned short)(u >> 16)));
}

// ---------------- kernel 1: split X, norms, H/L, init ----------------
__global__ void __launch_bounds__(256) prep_kernel(const float* __restrict__ X) {
    int row  = blockIdx.x * 8 + (threadIdx.x >> 5);
    int lane = threadIdx.x & 31;
    if (blockIdx.x == 0 && threadIdx.x == 0) g_nlist = 0;
    const float* xr = X + (size_t)row * DIM + lane * 8;
    float4 v0 = *(const float4*)xr;
    float4 v1 = *(const float4*)(xr + 4);
    float v[8] = {v0.x, v0.y, v0.z, v0.w, v1.x, v1.y, v1.z, v1.w};
    uint32_t ph[4], pl[4];
    float s = 0.f, hs = 0.f, ls = 0.f;
    #pragma unroll
    for (int q = 0; q < 4; q++) {
        float a = v[2 * q], b = v[2 * q + 1];
        __nv_bfloat16 ha = __float2bfloat16(a), hb = __float2bfloat16(b);
        float fha = __bfloat162float(ha), fhb = __bfloat162float(hb);
        float fla = a - fha, flb = b - fhb;
        __nv_bfloat16 la = __float2bfloat16(fla);
        __nv_bfloat16 lb = __float2bfloat16(flb);
        ph[q] = ((uint32_t)__bfloat16_as_ushort(hb) << 16) | __bfloat16_as_ushort(ha);
        pl[q] = ((uint32_t)__bfloat16_as_ushort(lb) << 16) | __bfloat16_as_ushort(la);
        s  = fmaf(a, a, fmaf(b, b, s));
        hs = fmaf(fha, fha, fmaf(fhb, fhb, hs));
        float ga = __bfloat162float(la), gb = __bfloat162float(lb);
        ls = fmaf(ga, ga, fmaf(gb, gb, ls));
    }
    size_t off = (size_t)row * DIM + lane * 8;
    *(uint4*)(g_Xhi + off) = make_uint4(ph[0], ph[1], ph[2], ph[3]);
    *(uint4*)(g_Xlo + off) = make_uint4(pl[0], pl[1], pl[2], pl[3]);
    #pragma unroll
    for (int o = 16; o; o >>= 1) {
        s  += __shfl_xor_sync(0xffffffffu, s, o);
        hs += __shfl_xor_sync(0xffffffffu, hs, o);
        ls += __shfl_xor_sync(0xffffffffu, ls, o);
    }
    if (lane == 0) {
        g_sq[row] = s;
        g_H[row] = sqrtf(hs) * 1.0001f;
        g_L[row] = sqrtf(ls) * 1.0001f + 1e-6f;
    }
    if (lane < NTC) g_top4[(size_t)row * NTC + lane] =
        make_float4(INFINITY, INFINITY, INFINITY, INFINITY);
    if (lane == 8) g_cnt[row] = 0;
}

// ---------------- kernel 1b: class permutation ----------------
__global__ void perm_kernel(const int* __restrict__ y) {
    __shared__ int cnt[NCLS], base[NCLS];
    const int tid = threadIdx.x;
    if (tid < NCLS) cnt[tid] = 0;
    __syncthreads();
    for (int i = tid; i < NPTS; i += 1024) atomicAdd(&cnt[y[i]], 1);
    __syncthreads();
    if (tid == 0) {
        int b = 0;
        for (int c = 0; c < NCLS; c++) {
            base[c] = b; g_cbase[c] = b; g_ccnt[c] = cnt[c]; b += cnt[c];
        }
    }
    __syncthreads();
    if (tid < NCLS) cnt[tid] = 0;
    __syncthreads();
    for (int i = tid; i < NPTS; i += 1024) {
        int c = y[i];
        int pos = base[c] + atomicAdd(&cnt[c], 1);
        g_perm[pos] = i;
    }
}

// ---------------- shared GEMM config ----------------
#define TPITCH   80
#define TILE_SB  (128 * TPITCH)
#define STAGE_SB (4 * TILE_SB)
#define BUFPITCH 132
#define S4OFF    (128 * BUFPITCH * 4)
#define S4IOFF   (S4OFF + 4096)
#define GSMEM    (2 * STAGE_SB)            // 81920 B (classA)
// gemmB: K-chunk 64, rows of 64 bf16 = 128 B + 16 B pad
#define TPITCHB  144
#define TILE_B2  (128 * TPITCHB)           // 18432
#define STAGE_B2 (2 * TILE_B2)             // 36864 (Ahh + Bhh)
#define GSMEMB   (2 * STAGE_B2)            // 73728

// ---------------- kernel 2: phase A — class-grouped 3-term GEMM -> top-4+idx -------
__global__ void __launch_bounds__(256) classA_kernel() {
    extern __shared__ char smem[];
    __shared__ int pr[128], pc[128];
    const int tid = threadIdx.x, wid = tid >> 5, lane = tid & 31;
    const int warp_m = wid >> 2, warp_n = wid & 3;

    const int cls = blockIdx.x / CTRI;
    int t = blockIdx.x % CTRI;
    int ti = 0;
    while (t >= NTC - ti) { t -= NTC - ti; ti++; }
    const int tj = ti + t;
    const int nc = g_ccnt[cls];
    const int ntc = (nc + 127) >> 7;
    if (tj >= ntc) return;
    const int base = g_cbase[cls];

    if (tid < 128) {
        int p = ti * 128 + tid;
        pr[tid] = g_perm[base + min(p, nc - 1)];
    } else {
        int p = tj * 128 + (tid - 128);
        pc[tid - 128] = g_perm[base + min(p, nc - 1)];
    }
    __syncthreads();

    const uint32_t sb = smem_u32(smem);

    auto load_stage = [&](int stage, int kc) {
        uint32_t bA = sb + stage * STAGE_SB;
        #pragma unroll
        for (int i = 0; i < 8; i++) {
            int gid = tid + i * 256;
            int tile = gid >> 9, rem = gid & 511;
            int r = rem >> 2, c = rem & 3;
            int grow = (tile < 2) ? pr[r] : pc[r];
            const __nv_bfloat16* src = ((tile & 1) ? g_Xlo : g_Xhi)
                                     + (size_t)grow * DIM + kc * 32 + c * 8;
            cp16(bA + tile * TILE_SB + r * TPITCH + c * 16, src);
        }
        CP_COMMIT();
    };

    float acc[4][4][4];
    #pragma unroll
    for (int mt = 0; mt < 4; mt++)
        #pragma unroll
        for (int nt = 0; nt < 4; nt++)
            #pragma unroll
            for (int e = 0; e < 4; e++) acc[mt][nt][e] = 0.f;

    load_stage(0, 0);
    CP_WAIT0(); __syncthreads();
    #pragma unroll 1
    for (int kc = 0; kc < 8; kc++) {
        if (kc < 7) load_stage((kc + 1) & 1, kc + 1);
        const uint32_t st = sb + (kc & 1) * STAGE_SB;
        #pragma unroll
        for (int ks = 0; ks < 2; ks++) {
            uint32_t ah[4][4], al[4][4], bh[4][2], bl[4][2];
            const uint32_t a_l16 = lane & 15, a_hi16 = (lane >> 4) * 16;
            #pragma unroll
            for (int mt = 0; mt < 4; mt++) {
                uint32_t rowa = warp_m * 64 + mt * 16 + a_l16;
                uint32_t ad = st + rowa * TPITCH + ks * 32 + a_hi16;
                ldsm_x4(ah[mt], ad);
                ldsm_x4(al[mt], ad + TILE_SB);
            }
            const uint32_t g = lane >> 3;
            const uint32_t b_boff = (g & 1) * 16;
            #pragma unroll
            for (int np = 0; np < 2; np++) {
                uint32_t rown = warp_n * 32 + np * 16 + (g >> 1) * 8 + (lane & 7);
                uint32_t bd = st + 2 * TILE_SB + rown * TPITCH + ks * 32 + b_boff;
                uint32_t tb[4];
                ldsm_x4(tb, bd);
                bh[2*np][0] = tb[0]; bh[2*np][1] = tb[1];
                bh[2*np+1][0] = tb[2]; bh[2*np+1][1] = tb[3];
                ldsm_x4(tb, bd + TILE_SB);
                bl[2*np][0] = tb[0]; bl[2*np][1] = tb[1];
                bl[2*np+1][0] = tb[2]; bl[2*np+1][1] = tb[3];
            }
            #pragma unroll
            for (int mt = 0; mt < 4; mt++)
                #pragma unroll
                for (int nt = 0; nt < 4; nt++)
                    MMA16816(acc[mt][nt], ah[mt], bh[nt]);
            #pragma unroll
            for (int mt = 0; mt < 4; mt++)
                #pragma unroll
                for (int nt = 0; nt < 4; nt++)
                    MMA16816(acc[mt][nt], ah[mt], bl[nt]);
            #pragma unroll
            for (int mt = 0; mt < 4; mt++)
                #pragma unroll
                for (int nt = 0; nt < 4; nt++)
                    MMA16816(acc[mt][nt], al[mt], bh[nt]);
        }
        if (kc < 7) { CP_WAIT0(); __syncthreads(); }
    }
    __syncthreads();

    const int frag_r = lane >> 2, frag_k = lane & 3;
    float sqi[8], sqj[8];
    #pragma unroll
    for (int mt = 0; mt < 4; mt++) {
        sqi[2 * mt]     = g_sq[pr[warp_m * 64 + mt * 16 + frag_r]];
        sqi[2 * mt + 1] = g_sq[pr[warp_m * 64 + mt * 16 + frag_r + 8]];
    }
    #pragma unroll
    for (int nt = 0; nt < 4; nt++) {
        sqj[2 * nt]     = g_sq[pc[warp_n * 32 + nt * 8 + 2 * frag_k]];
        sqj[2 * nt + 1] = g_sq[pc[warp_n * 32 + nt * 8 + 2 * frag_k + 1]];
    }

    float* buf = (float*)smem;
    #pragma unroll
    for (int mt = 0; mt < 4; mt++) {
        int r0 = warp_m * 64 + mt * 16 + frag_r;
        #pragma unroll
        for (int nt = 0; nt < 4; nt++) {
            int c0 = warp_n * 32 + nt * 8 + 2 * frag_k;
            buf[r0 * BUFPITCH + c0]           = fmaxf(fmaf(-2.f, acc[mt][nt][0], sqi[2*mt]   + sqj[2*nt]),   0.f);
            buf[r0 * BUFPITCH + c0 + 1]       = fmaxf(fmaf(-2.f, acc[mt][nt][1], sqi[2*mt]   + sqj[2*nt+1]), 0.f);
            buf[(r0 + 8) * BUFPITCH + c0]     = fmaxf(fmaf(-2.f, acc[mt][nt][2], sqi[2*mt+1] + sqj[2*nt]),   0.f);
            buf[(r0 + 8) * BUFPITCH + c0 + 1] = fmaxf(fmaf(-2.f, acc[mt][nt][3], sqi[2*mt+1] + sqj[2*nt+1]), 0.f);
        }
    }
    __syncthreads();

    float4* s4 = (float4*)(smem + S4OFF);
    int4*   s4i = (int4*)(smem + S4IOFF);
    const int rowlim = nc - ti * 128;
    const int collim = nc - tj * 128;

    {
        int r = tid >> 1, h = tid & 1;
        const float* br = buf + r * BUFPITCH + h * 64;
        float bv[4] = {INFINITY, INFINITY, INFINITY, INFINITY};
        int bidx[4] = {0, 0, 0, 0};
        int lim = min(64, collim - h * 64);
        for (int s = 0; s < lim; s++) ins4i(br[s], pc[h * 64 + s], bv, bidx);
        s4[tid] = make_float4(bv[0], bv[1], bv[2], bv[3]);
        s4i[tid] = make_int4(bidx[0], bidx[1], bidx[2], bidx[3]);
    }
    __syncthreads();
    if ((tid & 1) == 0) {
        int r = tid >> 1;
        if (r < rowlim) {
            float av[4] = {s4[tid].x, s4[tid].y, s4[tid].z, s4[tid].w};
            int   ai[4] = {s4i[tid].x, s4i[tid].y, s4i[tid].z, s4i[tid].w};
            float bv[4] = {s4[tid+1].x, s4[tid+1].y, s4[tid+1].z, s4[tid+1].w};
            int   bidx[4] = {s4i[tid+1].x, s4i[tid+1].y, s4i[tid+1].z, s4i[tid+1].w};
            merge4i(av, ai, bv, bidx);
            g_top4[(size_t)pr[r] * NTC + tj] = make_float4(av[0], av[1], av[2], av[3]);
            g_top4i[(size_t)pr[r] * NTC + tj] = make_int4(ai[0], ai[1], ai[2], ai[3]);
        }
    }

    if (ti != tj) {
        __syncthreads();
        {
            int c = tid >> 1, h = tid & 1;
            float bv[4] = {INFINITY, INFINITY, INFINITY, INFINITY};
            int bidx[4] = {0, 0, 0, 0};
            int lim = min(64, rowlim - h * 64);
            for (int s = 0; s < lim; s++)
                ins4i(buf[(h * 64 + s) * BUFPITCH + c], pr[h * 64 + s], bv, bidx);
            s4[tid] = make_float4(bv[0], bv[1], bv[2], bv[3]);
            s4i[tid] = make_int4(bidx[0], bidx[1], bidx[2], bidx[3]);
        }
        __syncthreads();
        if ((tid & 1) == 0) {
            int c = tid >> 1;
            if (c < collim) {
                float av[4] = {s4[tid].x, s4[tid].y, s4[tid].z, s4[tid].w};
                int   ai[4] = {s4i[tid].x, s4i[tid].y, s4i[tid].z, s4i[tid].w};
                float bv[4] = {s4[tid+1].x, s4[tid+1].y, s4[tid+1].z, s4[tid+1].w};
                int   bidx[4] = {s4i[tid+1].x, s4i[tid+1].y, s4i[tid+1].z, s4i[tid+1].w};
                merge4i(av, ai, bv, bidx);
                g_top4[(size_t)pc[c] * NTC + ti] = make_float4(av[0], av[1], av[2], av[3]);
                g_top4i[(size_t)pc[c] * NTC + ti] = make_int4(ai[0], ai[1], ai[2], ai[3]);
            }
        }
    }
}

// ---------------- kernel 3: anchor reduce ----------------
__global__ void __launch_bounds__(128) anchor_kernel() {
    int row = blockIdx.x * 128 + threadIdx.x;
    float4 q = g_top4[(size_t)row * NTC];
    int4  qi = g_top4i[(size_t)row * NTC];
    float av[4] = {q.x, q.y, q.z, q.w};
    int   ai[4] = {qi.x, qi.y, qi.z, qi.w};
    #pragma unroll
    for (int t = 1; t < NTC; t++) {
        float4 w = g_top4[(size_t)row * NTC + t];
        int4  wi = g_top4i[(size_t)row * NTC + t];
        float bv[4] = {w.x, w.y, w.z, w.w};
        int   bidx[4] = {wi.x, wi.y, wi.z, wi.w};
        merge4i(av, ai, bv, bidx);
    }
    g_anchor[row] = av[3];
    g_anchi[row]  = ai[3];
}

// ---------------- kernel 4: phase B — hh-only GEMM (K-chunk 64) + interval count ---
__global__ void __launch_bounds__(256) gemmB_kernel() {
    extern __shared__ char smem[];
    __shared__ float s_anc[256], s_H[256], s_L[256];
    __shared__ int scnt[256];
    const int tid = threadIdx.x, wid = tid >> 5, lane = tid & 31;
    const int warp_m = wid >> 2, warp_n = wid & 3;

    int idx = blockIdx.x;
    int bi = (int)((2 * NT + 1 - sqrtf((float)((2 * NT + 1) * (2 * NT + 1) - 8 * idx))) * 0.5f);
    while ((bi + 1) * NT - ((bi + 1) * bi) / 2 <= idx) bi++;
    while (bi * NT - (bi * (bi - 1)) / 2 > idx) bi--;
    int bj = bi + (idx - (bi * NT - (bi * (bi - 1)) / 2));
    const int row0 = bi * 128, col0 = bj * 128;

    const uint32_t sb = smem_u32(smem);

    // K-chunk 64: 2048 cp16 per stage, 8 per thread
    auto load_stage = [&](int stage, int kc) {
        uint32_t bA = sb + stage * STAGE_B2;
        #pragma unroll
        for (int i = 0; i < 8; i++) {
            int gid = tid + i * 256;
            int tile = gid >> 10, rem = gid & 1023;
            int r = rem >> 3, c = rem & 7;
            const __nv_bfloat16* src = g_Xhi
                + (size_t)((tile ? col0 : row0) + r) * DIM + kc * 64 + c * 8;
            cp16(bA + tile * TILE_B2 + r * TPITCHB + c * 16, src);
        }
        CP_COMMIT();
    };

    load_stage(0, 0);
    {
        int r = (tid < 128) ? (row0 + tid) : (col0 + tid - 128);
        s_anc[tid] = g_anchor[r];
        s_H[tid]   = g_H[r];
        s_L[tid]   = g_L[r];
        scnt[tid] = 0;
    }

    float acc[4][4][4];
    #pragma unroll
    for (int mt = 0; mt < 4; mt++)
        #pragma unroll
        for (int nt = 0; nt < 4; nt++)
            #pragma unroll
            for (int e = 0; e < 4; e++) acc[mt][nt][e] = 0.f;

    CP_WAIT0(); __syncthreads();
    #pragma unroll 1
    for (int kc = 0; kc < 4; kc++) {
        if (kc < 3) load_stage((kc + 1) & 1, kc + 1);
        const uint32_t st = sb + (kc & 1) * STAGE_B2;
        #pragma unroll
        for (int ks = 0; ks < 4; ks++) {
            uint32_t ah[4][4], bh[4][2];
            const uint32_t a_l16 = lane & 15, a_hi16 = (lane >> 4) * 16;
            #pragma unroll
            for (int mt = 0; mt < 4; mt++) {
                uint32_t rowa = warp_m * 64 + mt * 16 + a_l16;
                ldsm_x4(ah[mt], st + rowa * TPITCHB + ks * 32 + a_hi16);
            }
            const uint32_t g = lane >> 3;
            const uint32_t b_boff = (g & 1) * 16;
            #pragma unroll
            for (int np = 0; np < 2; np++) {
                uint32_t rown = warp_n * 32 + np * 16 + (g >> 1) * 8 + (lane & 7);
                uint32_t tb[4];
                ldsm_x4(tb, st + TILE_B2 + rown * TPITCHB + ks * 32 + b_boff);
                bh[2*np][0] = tb[0]; bh[2*np][1] = tb[1];
                bh[2*np+1][0] = tb[2]; bh[2*np+1][1] = tb[3];
            }
            #pragma unroll
            for (int mt = 0; mt < 4; mt++)
                #pragma unroll
                for (int nt = 0; nt < 4; nt++)
                    MMA16816(acc[mt][nt], ah[mt], bh[nt]);
        }
        if (kc < 3) { CP_WAIT0(); __syncthreads(); }
    }

    const int frag_r = lane >> 2, frag_k = lane & 3;
    float sqi[8], sqj[8], ar[8], ac[8], hr[8], lr[8], hc[8], lc[8];
    #pragma unroll
    for (int mt = 0; mt < 4; mt++) {
        int r = warp_m * 64 + mt * 16 + frag_r;
        sqi[2*mt] = g_sq[row0 + r]; sqi[2*mt+1] = g_sq[row0 + r + 8];
        ar[2*mt]  = s_anc[r];       ar[2*mt+1]  = s_anc[r + 8];
        hr[2*mt]  = s_H[r];         hr[2*mt+1]  = s_H[r + 8];
        lr[2*mt]  = s_L[r];         lr[2*mt+1]  = s_L[r + 8];
    }
    #pragma unroll
    for (int nt = 0; nt < 4; nt++) {
        int c = warp_n * 32 + nt * 8 + 2 * frag_k;
        sqj[2*nt] = g_sq[col0 + c]; sqj[2*nt+1] = g_sq[col0 + c + 1];
        ac[2*nt]  = s_anc[128 + c]; ac[2*nt+1]  = s_anc[128 + c + 1];
        hc[2*nt]  = s_H[128 + c];   hc[2*nt+1]  = s_H[128 + c + 1];
        lc[2*nt]  = s_L[128 + c];   lc[2*nt+1]  = s_L[128 + c + 1];
    }

    int rc[8] = {0,0,0,0,0,0,0,0}, cc[8] = {0,0,0,0,0,0,0,0};
    const bool offdiag = (bi != bj);

    auto push = [&](int center, int other) {
        int pos = atomicAdd(&g_nlist, 1);
        if (pos < LCAP) g_list[pos] = ((uint32_t)center << 13) | (uint32_t)other;
    };
    auto cls = [&](float d, float bnd, float anr, float anc2, int r, int c,
                   int& rcnt, int& ccnt) {
        if (d < anr - bnd) rcnt++;
        else if (d < anr + bnd) push(row0 + r, col0 + c);
        if (offdiag) {
            if (d < anc2 - bnd) ccnt++;
            else if (d < anc2 + bnd) push(col0 + c, row0 + r);
        }
    };

    #pragma unroll
    for (int mt = 0; mt < 4; mt++) {
        int r = warp_m * 64 + mt * 16 + frag_r;
        #pragma unroll
        for (int nt = 0; nt < 4; nt++) {
            int c = warp_n * 32 + nt * 8 + 2 * frag_k;
            float d00 = fmaxf(fmaf(-2.f, acc[mt][nt][0], sqi[2*mt]   + sqj[2*nt]),   0.f);
            float d01 = fmaxf(fmaf(-2.f, acc[mt][nt][1], sqi[2*mt]   + sqj[2*nt+1]), 0.f);
            float d10 = fmaxf(fmaf(-2.f, acc[mt][nt][2], sqi[2*mt+1] + sqj[2*nt]),   0.f);
            float d11 = fmaxf(fmaf(-2.f, acc[mt][nt][3], sqi[2*mt+1] + sqj[2*nt+1]), 0.f);
            float b00 = 2.f * fmaf(hr[2*mt],   lc[2*nt],   lr[2*mt]   * hc[2*nt])   + BMARGIN;
            float b01 = 2.f * fmaf(hr[2*mt],   lc[2*nt+1], lr[2*mt]   * hc[2*nt+1]) + BMARGIN;
            float b10 = 2.f * fmaf(hr[2*mt+1], lc[2*nt],   lr[2*mt+1] * hc[2*nt])   + BMARGIN;
            float b11 = 2.f * fmaf(hr[2*mt+1], lc[2*nt+1], lr[2*mt+1] * hc[2*nt+1]) + BMARGIN;
            cls(d00, b00, ar[2*mt],   ac[2*nt],   r,     c,     rc[2*mt],   cc[2*nt]);
            cls(d01, b01, ar[2*mt],   ac[2*nt+1], r,     c + 1, rc[2*mt],   cc[2*nt+1]);
            cls(d10, b10, ar[2*mt+1], ac[2*nt],   r + 8, c,     rc[2*mt+1], cc[2*nt]);
            cls(d11, b11, ar[2*mt+1], ac[2*nt+1], r + 8, c + 1, rc[2*mt+1], cc[2*nt+1]);
        }
    }

    __syncthreads();
    #pragma unroll
    for (int mt = 0; mt < 4; mt++) {
        int r = warp_m * 64 + mt * 16 + frag_r;
        atomicAdd(&scnt[r], rc[2 * mt]);
        atomicAdd(&scnt[r + 8], rc[2 * mt + 1]);
    }
    if (offdiag) {
        #pragma unroll
        for (int nt = 0; nt < 4; nt++) {
            int c = warp_n * 32 + nt * 8 + 2 * frag_k;
            atomicAdd(&scnt[128 + c], cc[2 * nt]);
            atomicAdd(&scnt[128 + c + 1], cc[2 * nt + 1]);
        }
    }
    __syncthreads();
    if (tid < 128) atomicAdd(&g_cnt[row0 + tid], scnt[tid]);
    else if (offdiag) atomicAdd(&g_cnt[col0 + tid - 128], scnt[tid]);
}

// ---------------- kernel 5: fixup — resolve ambiguous pairs exactly ----------------
__global__ void __launch_bounds__(256) fixup_kernel() {
    const int lane = threadIdx.x & 31;
    const int gw = (blockIdx.x * 256 + threadIdx.x) >> 5;
    const int nw = gridDim.x * 8;
    int n = g_nlist;
    if (n > LCAP) n = LCAP;

    for (int e = gw; e < n; e += nw) {
        uint32_t pk = g_list[e];
        int i = pk >> 13, j = pk & 8191;
        uint4 hi_i = ((const uint4*)(g_Xhi + (size_t)i * DIM))[lane];
        uint4 lo_i = ((const uint4*)(g_Xlo + (size_t)i * DIM))[lane];
        uint4 hi_j = ((const uint4*)(g_Xhi + (size_t)j * DIM))[lane];
        uint4 lo_j = ((const uint4*)(g_Xlo + (size_t)j * DIM))[lane];
        uint32_t ha[4] = {hi_i.x, hi_i.y, hi_i.z, hi_i.w};
        uint32_t la[4] = {lo_i.x, lo_i.y, lo_i.z, lo_i.w};
        uint32_t hb[4] = {hi_j.x, hi_j.y, hi_j.z, hi_j.w};
        uint32_t lb[4] = {lo_j.x, lo_j.y, lo_j.z, lo_j.w};
        float dhh = 0.f, dhl = 0.f, dlh = 0.f;
        #pragma unroll
        for (int w = 0; w < 4; w++) {
            float hia = b_lo(ha[w]), hib = b_hi(ha[w]);
            float lia = b_lo(la[w]), lib = b_hi(la[w]);
            float hja = b_lo(hb[w]), hjb = b_hi(hb[w]);
            float lja = b_lo(lb[w]), ljb = b_hi(lb[w]);
            dhh = fmaf(hia, hja, fmaf(hib, hjb, dhh));
            dhl = fmaf(hia, lja, fmaf(hib, ljb, dhl));
            dlh = fmaf(lia, hja, fmaf(lib, hjb, dlh));
        }
        #pragma unroll
        for (int o = 16; o; o >>= 1) {
            dhh += __shfl_xor_sync(0xffffffffu, dhh, o);
            dhl += __shfl_xor_sync(0xffffffffu, dhl, o);
            dlh += __shfl_xor_sync(0xffffffffu, dlh, o);
        }
        if (lane == 0) {
            float dot = (dhh + dhl) + dlh;
            float d2s = fmaxf(fmaf(-2.f, dot, g_sq[i] + g_sq[j]), 0.f);
            if (j != g_anchi[i] && d2s < g_anchor[i])
                atomicAdd(&g_cnt[i], 1);
        }
    }
}

// ---------------- kernel 6: finalize ----------------
__device__ double digamma_d(double x) {
    double r = 0.0;
    while (x < 6.0) { r -= 1.0 / x; x += 1.0; }
    double f = 1.0 / (x * x);
    double ser = f * (1.0 / 12.0 - f * (1.0 / 120.0 - f * (1.0 / 252.0
               - f * (1.0 / 240.0 - f * (1.0 / 132.0)))));
    return r + log(x) - 0.5 / x - ser;
}

__global__ void fin_part_kernel() {
    __shared__ double sd[128];
    const int tid = threadIdx.x;
    int r = blockIdx.x * 128 + tid;
    float arg = (float)(g_cnt[r] - 1) + 1e-7f;
    sd[tid] = digamma_d((double)arg);
    __syncthreads();
    for (int off = 64; off; off >>= 1) {
        if (tid < off) sd[tid] += sd[tid + off];
        __syncthreads();
    }
    if (tid == 0) g_part[blockIdx.x] = sd[0];
}

__global__ void fin2_kernel(const int* __restrict__ y, float* __restrict__ out) {
    __shared__ int hist[NCLS];
    const int tid = threadIdx.x;
    if (tid < NCLS) hist[tid] = 0;
    __syncthreads();
    for (int j = tid; j < NPTS; j += 256) atomicAdd(&hist[y[j]], 1);
    __syncthreads();
    if (tid == 0) {
        double s = 0.0;
        for (int b = 0; b < 64; b++) s += g_part[b];
        double avg_m = s / (double)NPTS;
        double avg_Nx = 0.0;
        for (int c = 0; c < NCLS; c++) {
            double nx = (double)hist[c];
            avg_Nx += (nx / (double)NPTS) * digamma_d(nx);
        }
        double mi = (digamma_d((double)NPTS) - avg_Nx
                   + digamma_d((double)KNN) - avg_m) / log(2.0);
        if (mi < 0.0) mi = 0.0;
        out[0] = (float)mi;
    }
}

// ---------------- launch ----------------
extern "C" void kernel_launch(void* const* d_in, const int* in_sizes, int n_in,
                              void* d_out, int out_size) {
    const float* X = (const float*)d_in[0];
    const int*   y = (const int*)d_in[1];
    float* out = (float*)d_out;
    (void)in_sizes; (void)n_in; (void)out_size;

    cudaFuncSetAttribute(classA_kernel, cudaFuncAttributeMaxDynamicSharedMemorySize, GSMEM);
    cudaFuncSetAttribute(gemmB_kernel,  cudaFuncAttributeMaxDynamicSharedMemorySize, GSMEMB);

    prep_kernel<<<NPTS / 8, 256>>>(X);
    perm_kernel<<<1, 1024>>>(y);
    classA_kernel<<<NCLS * CTRI, 256, GSMEM>>>();
    anchor_kernel<<<NPTS / 128, 128>>>();
    gemmB_kernel<<<NTRI, 256, GSMEMB>>>();
    fixup_kernel<<<512, 256>>>();
    fin_part_kernel<<<64, 128>>>();
    fin2_kernel<<<1, 256>>>(y, out);
}

// round 13
// speedup vs baseline: 1.2808x; 1.2808x over previous
#include <cuda_runtime.h>
#include <cuda_bf16.h>
#include <cstdint>
#include <math.h>

#define NPTS 8192
#define DIM  256
#define NCLS 10
#define KNN  3
#define NT   64
#define NTRI (NT*(NT+1)/2)
#define NTC  8
#define CTRI (NTC*(NTC+1)/2)
#define LCAP (1 << 20)
#define PCAP 1024
#define BMARGIN 0.1f

// ---------------- device scratch ----------------
__device__ float g_sq[NPTS];
__device__ float g_H[NPTS];
__device__ float g_L[NPTS];
__device__ int   g_cnt[NPTS];
__device__ float g_anchor[NPTS];
__device__ int   g_anchi[NPTS];
__device__ float4 g_top4[(size_t)NPTS * NTC];
__device__ int4   g_top4i[(size_t)NPTS * NTC];
__device__ double g_part[64];
__device__ __nv_bfloat16 g_Xhi[(size_t)NPTS * DIM];
__device__ __nv_bfloat16 g_Xlo[(size_t)NPTS * DIM];
__device__ int g_perm[NPTS];
__device__ int g_cbase[NCLS];
__device__ int g_ccnt[NCLS];
__device__ int g_nlist;
__device__ uint32_t g_list[LCAP];

// ---------------- helpers ----------------
__device__ __forceinline__ uint32_t smem_u32(const void* p) {
    uint32_t a;
    asm("{ .reg .u64 t; cvta.to.shared.u64 t, %1; cvt.u32.u64 %0, t; }" : "=r"(a) : "l"(p));
    return a;
}
__device__ __forceinline__ void cp16(uint32_t dst, const void* src) {
    asm volatile("cp.async.cg.shared.global [%0], [%1], 16;" :: "r"(dst), "l"(src));
}
#define CP_COMMIT() asm volatile("cp.async.commit_group;" ::: "memory")
#define CP_WAIT0()  asm volatile("cp.async.wait_group 0;" ::: "memory")

#define MMA16816(d, a, b) \
  asm volatile("mma.sync.aligned.m16n8k16.row.col.f32.bf16.bf16.f32 " \
      "{%0,%1,%2,%3}, {%4,%5,%6,%7}, {%8,%9}, {%0,%1,%2,%3};" \
      : "+f"(d[0]), "+f"(d[1]), "+f"(d[2]), "+f"(d[3]) \
      : "r"(a[0]), "r"(a[1]), "r"(a[2]), "r"(a[3]), "r"(b[0]), "r"(b[1]))

__device__ __forceinline__ void ldsm_x4(uint32_t* r, uint32_t addr) {
    asm volatile("ldmatrix.sync.aligned.m8n8.x4.shared.b16 {%0,%1,%2,%3}, [%4];"
        : "=r"(r[0]), "=r"(r[1]), "=r"(r[2]), "=r"(r[3]) : "r"(addr));
}

__device__ __forceinline__ void ins4i(float v, int id, float* b, int* bi) {
    if (v < b[3]) {
        if (v < b[2]) {
            b[3] = b[2]; bi[3] = bi[2];
            if (v < b[1]) {
                b[2] = b[1]; bi[2] = bi[1];
                if (v < b[0]) { b[1] = b[0]; bi[1] = bi[0]; b[0] = v; bi[0] = id; }
                else          { b[1] = v; bi[1] = id; }
            } else { b[2] = v; bi[2] = id; }
        } else { b[3] = v; bi[3] = id; }
    }
}
__device__ __forceinline__ void merge4i(float* a, int* ai, const float* b, const int* bi) {
    float rv[4]; int ri[4];
    int x = 0, y = 0;
    #pragma unroll
    for (int t = 0; t < 4; t++) {
        bool ta = (y >= 4) || (x < 4 && a[x] <= b[y]);
        if (ta) { rv[t] = a[x]; ri[t] = ai[x]; x++; }
        else    { rv[t] = b[y]; ri[t] = bi[y]; y++; }
    }
    #pragma unroll
    for (int t = 0; t < 4; t++) { a[t] = rv[t]; ai[t] = ri[t]; }
}
__device__ __forceinline__ float b_lo(uint32_t u) {
    return __bfloat162float(__ushort_as_bfloat16((unsigned short)(u & 0xffffu)));
}
__device__ __forceinline__ float b_hi(uint32_t u) {
    return __bfloat162float(__ushort_as_bfloat16((unsigned short)(u >> 16)));
}

// ---------------- kernel 1: split X, norms, H/L, init ----------------
__global__ void __launch_bounds__(256) prep_kernel(const float* __restrict__ X) {
    int row  = blockIdx.x * 8 + (threadIdx.x >> 5);
    int lane = threadIdx.x & 31;
    if (blockIdx.x == 0 && threadIdx.x == 0) g_nlist = 0;
    const float* xr = X + (size_t)row * DIM + lane * 8;
    float4 v0 = *(const float4*)xr;
    float4 v1 = *(const float4*)(xr + 4);
    float v[8] = {v0.x, v0.y, v0.z, v0.w, v1.x, v1.y, v1.z, v1.w};
    uint32_t ph[4], pl[4];
    float s = 0.f, hs = 0.f, ls = 0.f;
    #pragma unroll
    for (int q = 0; q < 4; q++) {
        float a = v[2 * q], b = v[2 * q + 1];
        __nv_bfloat16 ha = __float2bfloat16(a), hb = __float2bfloat16(b);
        float fha = __bfloat162float(ha), fhb = __bfloat162float(hb);
        float fla = a - fha, flb = b - fhb;
        __nv_bfloat16 la = __float2bfloat16(fla);
        __nv_bfloat16 lb = __float2bfloat16(flb);
        ph[q] = ((uint32_t)__bfloat16_as_ushort(hb) << 16) | __bfloat16_as_ushort(ha);
        pl[q] = ((uint32_t)__bfloat16_as_ushort(lb) << 16) | __bfloat16_as_ushort(la);
        s  = fmaf(a, a, fmaf(b, b, s));
        hs = fmaf(fha, fha, fmaf(fhb, fhb, hs));
        float ga = __bfloat162float(la), gb = __bfloat162float(lb);
        ls = fmaf(ga, ga, fmaf(gb, gb, ls));
    }
    size_t off = (size_t)row * DIM + lane * 8;
    *(uint4*)(g_Xhi + off) = make_uint4(ph[0], ph[1], ph[2], ph[3]);
    *(uint4*)(g_Xlo + off) = make_uint4(pl[0], pl[1], pl[2], pl[3]);
    #pragma unroll
    for (int o = 16; o; o >>= 1) {
        s  += __shfl_xor_sync(0xffffffffu, s, o);
        hs += __shfl_xor_sync(0xffffffffu, hs, o);
        ls += __shfl_xor_sync(0xffffffffu, ls, o);
    }
    if (lane == 0) {
        g_sq[row] = s;
        g_H[row] = sqrtf(hs) * 1.0001f;
        g_L[row] = sqrtf(ls) * 1.0001f + 1e-6f;
    }
    if (lane < NTC) g_top4[(size_t)row * NTC + lane] =
        make_float4(INFINITY, INFINITY, INFINITY, INFINITY);
    if (lane == 8) g_cnt[row] = 0;
}

// ---------------- kernel 1b: class permutation ----------------
__global__ void perm_kernel(const int* __restrict__ y) {
    __shared__ int cnt[NCLS], base[NCLS];
    const int tid = threadIdx.x;
    if (tid < NCLS) cnt[tid] = 0;
    __syncthreads();
    for (int i = tid; i < NPTS; i += 1024) atomicAdd(&cnt[y[i]], 1);
    __syncthreads();
    if (tid == 0) {
        int b = 0;
        for (int c = 0; c < NCLS; c++) {
            base[c] = b; g_cbase[c] = b; g_ccnt[c] = cnt[c]; b += cnt[c];
        }
    }
    __syncthreads();
    if (tid < NCLS) cnt[tid] = 0;
    __syncthreads();
    for (int i = tid; i < NPTS; i += 1024) {
        int c = y[i];
        int pos = base[c] + atomicAdd(&cnt[c], 1);
        g_perm[pos] = i;
    }
}

// ---------------- shared GEMM config ----------------
#define TPITCH   80
#define TILE_SB  (128 * TPITCH)
#define STAGE_SB (4 * TILE_SB)
#define BUFPITCH 132
#define S4OFF    (128 * BUFPITCH * 4)
#define S4IOFF   (S4OFF + 4096)
#define GSMEM    (2 * STAGE_SB)            // 81920 B (classA)
#define STAGE_B2 (2 * TILE_SB)             // hh-only stage
#define GSMEMB   (2 * STAGE_B2)            // 40960 B (gemmB)

// ---------------- kernel 2: phase A — class-grouped 3-term GEMM -> top-4+idx -------
__global__ void __launch_bounds__(256) classA_kernel() {
    extern __shared__ char smem[];
    __shared__ int pr[128], pc[128];
    const int tid = threadIdx.x, wid = tid >> 5, lane = tid & 31;
    const int warp_m = wid >> 2, warp_n = wid & 3;

    const int cls = blockIdx.x / CTRI;
    int t = blockIdx.x % CTRI;
    int ti = 0;
    while (t >= NTC - ti) { t -= NTC - ti; ti++; }
    const int tj = ti + t;
    const int nc = g_ccnt[cls];
    const int ntc = (nc + 127) >> 7;
    if (tj >= ntc) return;
    const int base = g_cbase[cls];

    if (tid < 128) {
        int p = ti * 128 + tid;
        pr[tid] = g_perm[base + min(p, nc - 1)];
    } else {
        int p = tj * 128 + (tid - 128);
        pc[tid - 128] = g_perm[base + min(p, nc - 1)];
    }
    __syncthreads();

    const uint32_t sb = smem_u32(smem);

    auto load_stage = [&](int stage, int kc) {
        uint32_t bA = sb + stage * STAGE_SB;
        #pragma unroll
        for (int i = 0; i < 8; i++) {
            int gid = tid + i * 256;
            int tile = gid >> 9, rem = gid & 511;
            int r = rem >> 2, c = rem & 3;
            int grow = (tile < 2) ? pr[r] : pc[r];
            const __nv_bfloat16* src = ((tile & 1) ? g_Xlo : g_Xhi)
                                     + (size_t)grow * DIM + kc * 32 + c * 8;
            cp16(bA + tile * TILE_SB + r * TPITCH + c * 16, src);
        }
        CP_COMMIT();
    };

    float acc[4][4][4];
    #pragma unroll
    for (int mt = 0; mt < 4; mt++)
        #pragma unroll
        for (int nt = 0; nt < 4; nt++)
            #pragma unroll
            for (int e = 0; e < 4; e++) acc[mt][nt][e] = 0.f;

    load_stage(0, 0);
    CP_WAIT0(); __syncthreads();
    #pragma unroll 1
    for (int kc = 0; kc < 8; kc++) {
        if (kc < 7) load_stage((kc + 1) & 1, kc + 1);
        const uint32_t st = sb + (kc & 1) * STAGE_SB;
        #pragma unroll
        for (int ks = 0; ks < 2; ks++) {
            uint32_t ah[4][4], al[4][4], bh[4][2], bl[4][2];
            const uint32_t a_l16 = lane & 15, a_hi16 = (lane >> 4) * 16;
            #pragma unroll
            for (int mt = 0; mt < 4; mt++) {
                uint32_t rowa = warp_m * 64 + mt * 16 + a_l16;
                uint32_t ad = st + rowa * TPITCH + ks * 32 + a_hi16;
                ldsm_x4(ah[mt], ad);
                ldsm_x4(al[mt], ad + TILE_SB);
            }
            const uint32_t g = lane >> 3;
            const uint32_t b_boff = (g & 1) * 16;
            #pragma unroll
            for (int np = 0; np < 2; np++) {
                uint32_t rown = warp_n * 32 + np * 16 + (g >> 1) * 8 + (lane & 7);
                uint32_t bd = st + 2 * TILE_SB + rown * TPITCH + ks * 32 + b_boff;
                uint32_t tb[4];
                ldsm_x4(tb, bd);
                bh[2*np][0] = tb[0]; bh[2*np][1] = tb[1];
                bh[2*np+1][0] = tb[2]; bh[2*np+1][1] = tb[3];
                ldsm_x4(tb, bd + TILE_SB);
                bl[2*np][0] = tb[0]; bl[2*np][1] = tb[1];
                bl[2*np+1][0] = tb[2]; bl[2*np+1][1] = tb[3];
            }
            #pragma unroll
            for (int mt = 0; mt < 4; mt++)
                #pragma unroll
                for (int nt = 0; nt < 4; nt++)
                    MMA16816(acc[mt][nt], ah[mt], bh[nt]);
            #pragma unroll
            for (int mt = 0; mt < 4; mt++)
                #pragma unroll
                for (int nt = 0; nt < 4; nt++)
                    MMA16816(acc[mt][nt], ah[mt], bl[nt]);
            #pragma unroll
            for (int mt = 0; mt < 4; mt++)
                #pragma unroll
                for (int nt = 0; nt < 4; nt++)
                    MMA16816(acc[mt][nt], al[mt], bh[nt]);
        }
        if (kc < 7) { CP_WAIT0(); __syncthreads(); }
    }
    __syncthreads();

    const int frag_r = lane >> 2, frag_k = lane & 3;
    float sqi[8], sqj[8];
    #pragma unroll
    for (int mt = 0; mt < 4; mt++) {
        sqi[2 * mt]     = g_sq[pr[warp_m * 64 + mt * 16 + frag_r]];
        sqi[2 * mt + 1] = g_sq[pr[warp_m * 64 + mt * 16 + frag_r + 8]];
    }
    #pragma unroll
    for (int nt = 0; nt < 4; nt++) {
        sqj[2 * nt]     = g_sq[pc[warp_n * 32 + nt * 8 + 2 * frag_k]];
        sqj[2 * nt + 1] = g_sq[pc[warp_n * 32 + nt * 8 + 2 * frag_k + 1]];
    }

    float* buf = (float*)smem;
    #pragma unroll
    for (int mt = 0; mt < 4; mt++) {
        int r0 = warp_m * 64 + mt * 16 + frag_r;
        #pragma unroll
        for (int nt = 0; nt < 4; nt++) {
            int c0 = warp_n * 32 + nt * 8 + 2 * frag_k;
            buf[r0 * BUFPITCH + c0]           = fmaxf(fmaf(-2.f, acc[mt][nt][0], sqi[2*mt]   + sqj[2*nt]),   0.f);
            buf[r0 * BUFPITCH + c0 + 1]       = fmaxf(fmaf(-2.f, acc[mt][nt][1], sqi[2*mt]   + sqj[2*nt+1]), 0.f);
            buf[(r0 + 8) * BUFPITCH + c0]     = fmaxf(fmaf(-2.f, acc[mt][nt][2], sqi[2*mt+1] + sqj[2*nt]),   0.f);
            buf[(r0 + 8) * BUFPITCH + c0 + 1] = fmaxf(fmaf(-2.f, acc[mt][nt][3], sqi[2*mt+1] + sqj[2*nt+1]), 0.f);
        }
    }
    __syncthreads();

    float4* s4 = (float4*)(smem + S4OFF);
    int4*   s4i = (int4*)(smem + S4IOFF);
    const int rowlim = nc - ti * 128;
    const int collim = nc - tj * 128;

    {
        int r = tid >> 1, h = tid & 1;
        const float* br = buf + r * BUFPITCH + h * 64;
        float bv[4] = {INFINITY, INFINITY, INFINITY, INFINITY};
        int bidx[4] = {0, 0, 0, 0};
        int lim = min(64, collim - h * 64);
        for (int s = 0; s < lim; s++) ins4i(br[s], pc[h * 64 + s], bv, bidx);
        s4[tid] = make_float4(bv[0], bv[1], bv[2], bv[3]);
        s4i[tid] = make_int4(bidx[0], bidx[1], bidx[2], bidx[3]);
    }
    __syncthreads();
    if ((tid & 1) == 0) {
        int r = tid >> 1;
        if (r < rowlim) {
            float av[4] = {s4[tid].x, s4[tid].y, s4[tid].z, s4[tid].w};
            int   ai[4] = {s4i[tid].x, s4i[tid].y, s4i[tid].z, s4i[tid].w};
            float bv[4] = {s4[tid+1].x, s4[tid+1].y, s4[tid+1].z, s4[tid+1].w};
            int   bidx[4] = {s4i[tid+1].x, s4i[tid+1].y, s4i[tid+1].z, s4i[tid+1].w};
            merge4i(av, ai, bv, bidx);
            g_top4[(size_t)pr[r] * NTC + tj] = make_float4(av[0], av[1], av[2], av[3]);
            g_top4i[(size_t)pr[r] * NTC + tj] = make_int4(ai[0], ai[1], ai[2], ai[3]);
        }
    }

    if (ti != tj) {
        __syncthreads();
        {
            int c = tid >> 1, h = tid & 1;
            float bv[4] = {INFINITY, INFINITY, INFINITY, INFINITY};
            int bidx[4] = {0, 0, 0, 0};
            int lim = min(64, rowlim - h * 64);
            for (int s = 0; s < lim; s++)
                ins4i(buf[(h * 64 + s) * BUFPITCH + c], pr[h * 64 + s], bv, bidx);
            s4[tid] = make_float4(bv[0], bv[1], bv[2], bv[3]);
            s4i[tid] = make_int4(bidx[0], bidx[1], bidx[2], bidx[3]);
        }
        __syncthreads();
        if ((tid & 1) == 0) {
            int c = tid >> 1;
            if (c < collim) {
                float av[4] = {s4[tid].x, s4[tid].y, s4[tid].z, s4[tid].w};
                int   ai[4] = {s4i[tid].x, s4i[tid].y, s4i[tid].z, s4i[tid].w};
                float bv[4] = {s4[tid+1].x, s4[tid+1].y, s4[tid+1].z, s4[tid+1].w};
                int   bidx[4] = {s4i[tid+1].x, s4i[tid+1].y, s4i[tid+1].z, s4i[tid+1].w};
                merge4i(av, ai, bv, bidx);
                g_top4[(size_t)pc[c] * NTC + ti] = make_float4(av[0], av[1], av[2], av[3]);
                g_top4i[(size_t)pc[c] * NTC + ti] = make_int4(ai[0], ai[1], ai[2], ai[3]);
            }
        }
    }
}

// ---------------- kernel 3: anchor reduce ----------------
__global__ void __launch_bounds__(128) anchor_kernel() {
    int row = blockIdx.x * 128 + threadIdx.x;
    float4 q = g_top4[(size_t)row * NTC];
    int4  qi = g_top4i[(size_t)row * NTC];
    float av[4] = {q.x, q.y, q.z, q.w};
    int   ai[4] = {qi.x, qi.y, qi.z, qi.w};
    #pragma unroll
    for (int t = 1; t < NTC; t++) {
        float4 w = g_top4[(size_t)row * NTC + t];
        int4  wi = g_top4i[(size_t)row * NTC + t];
        float bv[4] = {w.x, w.y, w.z, w.w};
        int   bidx[4] = {wi.x, wi.y, wi.z, wi.w};
        merge4i(av, ai, bv, bidx);
    }
    g_anchor[row] = av[3];
    g_anchi[row]  = ai[3];
}

// ---------------- kernel 4: phase B — hh-only GEMM + interval count (smem push) ----
__global__ void __launch_bounds__(256) gemmB_kernel() {
    extern __shared__ char smem[];
    __shared__ float s_anc[256], s_H[256], s_L[256];
    __shared__ int scnt[256];
    __shared__ uint32_t s_push[PCAP];
    __shared__ int s_npush, s_base;
    const int tid = threadIdx.x, wid = tid >> 5, lane = tid & 31;
    const int warp_m = wid >> 2, warp_n = wid & 3;

    int idx = blockIdx.x;
    int bi = (int)((2 * NT + 1 - sqrtf((float)((2 * NT + 1) * (2 * NT + 1) - 8 * idx))) * 0.5f);
    while ((bi + 1) * NT - ((bi + 1) * bi) / 2 <= idx) bi++;
    while (bi * NT - (bi * (bi - 1)) / 2 > idx) bi--;
    int bj = bi + (idx - (bi * NT - (bi * (bi - 1)) / 2));
    const int row0 = bi * 128, col0 = bj * 128;

    const uint32_t sb = smem_u32(smem);

    auto load_stage = [&](int stage, int kc) {
        uint32_t bA = sb + stage * STAGE_B2;
        #pragma unroll
        for (int i = 0; i < 4; i++) {
            int gid = tid + i * 256;
            int tile = gid >> 9, rem = gid & 511;
            int r = rem >> 2, c = rem & 3;
            const __nv_bfloat16* src = g_Xhi
                + (size_t)(tile ? col0 : row0) * DIM + (size_t)r * DIM + kc * 32 + c * 8;
            cp16(bA + tile * TILE_SB + r * TPITCH + c * 16, src);
        }
        CP_COMMIT();
    };

    load_stage(0, 0);
    {
        int r = (tid < 128) ? (row0 + tid) : (col0 + tid - 128);
        s_anc[tid] = g_anchor[r];
        s_H[tid]   = g_H[r];
        s_L[tid]   = g_L[r];
        scnt[tid] = 0;
        if (tid == 0) s_npush = 0;
    }

    float acc[4][4][4];
    #pragma unroll
    for (int mt = 0; mt < 4; mt++)
        #pragma unroll
        for (int nt = 0; nt < 4; nt++)
            #pragma unroll
            for (int e = 0; e < 4; e++) acc[mt][nt][e] = 0.f;

    CP_WAIT0(); __syncthreads();
    #pragma unroll 1
    for (int kc = 0; kc < 8; kc++) {
        if (kc < 7) load_stage((kc + 1) & 1, kc + 1);
        const uint32_t st = sb + (kc & 1) * STAGE_B2;
        #pragma unroll
        for (int ks = 0; ks < 2; ks++) {
            uint32_t ah[4][4], bh[4][2];
            const uint32_t a_l16 = lane & 15, a_hi16 = (lane >> 4) * 16;
            #pragma unroll
            for (int mt = 0; mt < 4; mt++) {
                uint32_t rowa = warp_m * 64 + mt * 16 + a_l16;
                ldsm_x4(ah[mt], st + rowa * TPITCH + ks * 32 + a_hi16);
            }
            const uint32_t g = lane >> 3;
            const uint32_t b_boff = (g & 1) * 16;
            #pragma unroll
            for (int np = 0; np < 2; np++) {
                uint32_t rown = warp_n * 32 + np * 16 + (g >> 1) * 8 + (lane & 7);
                uint32_t tb[4];
                ldsm_x4(tb, st + TILE_SB + rown * TPITCH + ks * 32 + b_boff);
                bh[2*np][0] = tb[0]; bh[2*np][1] = tb[1];
                bh[2*np+1][0] = tb[2]; bh[2*np+1][1] = tb[3];
            }
            #pragma unroll
            for (int mt = 0; mt < 4; mt++)
                #pragma unroll
                for (int nt = 0; nt < 4; nt++)
                    MMA16816(acc[mt][nt], ah[mt], bh[nt]);
        }
        if (kc < 7) { CP_WAIT0(); __syncthreads(); }
    }

    const int frag_r = lane >> 2, frag_k = lane & 3;
    float sqi[8], sqj[8];
    #pragma unroll
    for (int mt = 0; mt < 4; mt++) {
        int r = warp_m * 64 + mt * 16 + frag_r;
        sqi[2 * mt] = g_sq[row0 + r]; sqi[2 * mt + 1] = g_sq[row0 + r + 8];
    }
    #pragma unroll
    for (int nt = 0; nt < 4; nt++) {
        int c = warp_n * 32 + nt * 8 + 2 * frag_k;
        sqj[2 * nt] = g_sq[col0 + c]; sqj[2 * nt + 1] = g_sq[col0 + c + 1];
    }

    int rc[8] = {0,0,0,0,0,0,0,0}, cc[8] = {0,0,0,0,0,0,0,0};
    const bool offdiag = (bi != bj);

    auto push = [&](int center, int other) {
        uint32_t pk = ((uint32_t)center << 13) | (uint32_t)other;
        int p = atomicAdd(&s_npush, 1);
        if (p < PCAP) {
            s_push[p] = pk;
        } else {
            int pos = atomicAdd(&g_nlist, 1);
            if (pos < LCAP) g_list[pos] = pk;
        }
    };
    auto cls = [&](float d, int r, int c, int& rcnt, int& ccnt) {
        float bnd = 2.f * fmaf(s_H[r], s_L[128 + c], s_L[r] * s_H[128 + c]) + BMARGIN;
        float anr = s_anc[r];
        if (d < anr - bnd) rcnt++;
        else if (d < anr + bnd) push(row0 + r, col0 + c);
        if (offdiag) {
            float anc2 = s_anc[128 + c];
            if (d < anc2 - bnd) ccnt++;
            else if (d < anc2 + bnd) push(col0 + c, row0 + r);
        }
    };

    #pragma unroll
    for (int mt = 0; mt < 4; mt++) {
        int r = warp_m * 64 + mt * 16 + frag_r;
        #pragma unroll
        for (int nt = 0; nt < 4; nt++) {
            int c = warp_n * 32 + nt * 8 + 2 * frag_k;
            float d00 = fmaxf(fmaf(-2.f, acc[mt][nt][0], sqi[2*mt]   + sqj[2*nt]),   0.f);
            float d01 = fmaxf(fmaf(-2.f, acc[mt][nt][1], sqi[2*mt]   + sqj[2*nt+1]), 0.f);
            float d10 = fmaxf(fmaf(-2.f, acc[mt][nt][2], sqi[2*mt+1] + sqj[2*nt]),   0.f);
            float d11 = fmaxf(fmaf(-2.f, acc[mt][nt][3], sqi[2*mt+1] + sqj[2*nt+1]), 0.f);
            cls(d00, r,     c,     rc[2*mt],   cc[2*nt]);
            cls(d01, r,     c + 1, rc[2*mt],   cc[2*nt+1]);
            cls(d10, r + 8, c,     rc[2*mt+1], cc[2*nt]);
            cls(d11, r + 8, c + 1, rc[2*mt+1], cc[2*nt+1]);
        }
    }

    __syncthreads();
    // bulk list flush: one global atomic per CTA
    if (tid == 0) {
        int np = min(s_npush, PCAP);
        s_base = atomicAdd(&g_nlist, np);
    }
    #pragma unroll
    for (int mt = 0; mt < 4; mt++) {
        int r = warp_m * 64 + mt * 16 + frag_r;
        atomicAdd(&scnt[r], rc[2 * mt]);
        atomicAdd(&scnt[r + 8], rc[2 * mt + 1]);
    }
    if (offdiag) {
        #pragma unroll
        for (int nt = 0; nt < 4; nt++) {
            int c = warp_n * 32 + nt * 8 + 2 * frag_k;
            atomicAdd(&scnt[128 + c], cc[2 * nt]);
            atomicAdd(&scnt[128 + c + 1], cc[2 * nt + 1]);
        }
    }
    __syncthreads();
    {
        int np = min(s_npush, PCAP);
        int bgl = s_base;
        for (int e = tid; e < np; e += 256)
            if (bgl + e < LCAP) g_list[bgl + e] = s_push[e];
    }
    if (tid < 128) atomicAdd(&g_cnt[row0 + tid], scnt[tid]);
    else if (offdiag) atomicAdd(&g_cnt[col0 + tid - 128], scnt[tid]);
}

// ---------------- kernel 5: fixup — resolve ambiguous pairs exactly ----------------
__global__ void __launch_bounds__(256) fixup_kernel() {
    const int lane = threadIdx.x & 31;
    const int gw = (blockIdx.x * 256 + threadIdx.x) >> 5;
    const int nw = gridDim.x * 8;
    int n = g_nlist;
    if (n > LCAP) n = LCAP;

    for (int e = gw; e < n; e += nw) {
        uint32_t pk = g_list[e];
        int i = pk >> 13, j = pk & 8191;
        uint4 hi_i = ((const uint4*)(g_Xhi + (size_t)i * DIM))[lane];
        uint4 lo_i = ((const uint4*)(g_Xlo + (size_t)i * DIM))[lane];
        uint4 hi_j = ((const uint4*)(g_Xhi + (size_t)j * DIM))[lane];
        uint4 lo_j = ((const uint4*)(g_Xlo + (size_t)j * DIM))[lane];
        uint32_t ha[4] = {hi_i.x, hi_i.y, hi_i.z, hi_i.w};
        uint32_t la[4] = {lo_i.x, lo_i.y, lo_i.z, lo_i.w};
        uint32_t hb[4] = {hi_j.x, hi_j.y, hi_j.z, hi_j.w};
        uint32_t lb[4] = {lo_j.x, lo_j.y, lo_j.z, lo_j.w};
        float dhh = 0.f, dhl = 0.f, dlh = 0.f;
        #pragma unroll
        for (int w = 0; w < 4; w++) {
            float hia = b_lo(ha[w]), hib = b_hi(ha[w]);
            float lia = b_lo(la[w]), lib = b_hi(la[w]);
            float hja = b_lo(hb[w]), hjb = b_hi(hb[w]);
            float lja = b_lo(lb[w]), ljb = b_hi(lb[w]);
            dhh = fmaf(hia, hja, fmaf(hib, hjb, dhh));
            dhl = fmaf(hia, lja, fmaf(hib, ljb, dhl));
            dlh = fmaf(lia, hja, fmaf(lib, hjb, dlh));
        }
        #pragma unroll
        for (int o = 16; o; o >>= 1) {
            dhh += __shfl_xor_sync(0xffffffffu, dhh, o);
            dhl += __shfl_xor_sync(0xffffffffu, dhl, o);
            dlh += __shfl_xor_sync(0xffffffffu, dlh, o);
        }
        if (lane == 0) {
            float dot = (dhh + dhl) + dlh;
            float d2s = fmaxf(fmaf(-2.f, dot, g_sq[i] + g_sq[j]), 0.f);
            if (j != g_anchi[i] && d2s < g_anchor[i])
                atomicAdd(&g_cnt[i], 1);
        }
    }
}

// ---------------- kernel 6: finalize ----------------
__device__ double digamma_d(double x) {
    double r = 0.0;
    while (x < 6.0) { r -= 1.0 / x; x += 1.0; }
    double f = 1.0 / (x * x);
    double ser = f * (1.0 / 12.0 - f * (1.0 / 120.0 - f * (1.0 / 252.0
               - f * (1.0 / 240.0 - f * (1.0 / 132.0)))));
    return r + log(x) - 0.5 / x - ser;
}

__global__ void fin_part_kernel() {
    __shared__ double sd[128];
    const int tid = threadIdx.x;
    int r = blockIdx.x * 128 + tid;
    float arg = (float)(g_cnt[r] - 1) + 1e-7f;
    sd[tid] = digamma_d((double)arg);
    __syncthreads();
    for (int off = 64; off; off >>= 1) {
        if (tid < off) sd[tid] += sd[tid + off];
        __syncthreads();
    }
    if (tid == 0) g_part[blockIdx.x] = sd[0];
}

__global__ void fin2_kernel(const int* __restrict__ y, float* __restrict__ out) {
    __shared__ int hist[NCLS];
    const int tid = threadIdx.x;
    if (tid < NCLS) hist[tid] = 0;
    __syncthreads();
    for (int j = tid; j < NPTS; j += 256) atomicAdd(&hist[y[j]], 1);
    __syncthreads();
    if (tid == 0) {
        double s = 0.0;
        for (int b = 0; b < 64; b++) s += g_part[b];
        double avg_m = s / (double)NPTS;
        double avg_Nx = 0.0;
        for (int c = 0; c < NCLS; c++) {
            double nx = (double)hist[c];
            avg_Nx += (nx / (double)NPTS) * digamma_d(nx);
        }
        double mi = (digamma_d((double)NPTS) - avg_Nx
                   + digamma_d((double)KNN) - avg_m) / log(2.0);
        if (mi < 0.0) mi = 0.0;
        out[0] = (float)mi;
    }
}

// ---------------- launch ----------------
extern "C" void kernel_launch(void* const* d_in, const int* in_sizes, int n_in,
                              void* d_out, int out_size) {
    const float* X = (const float*)d_in[0];
    const int*   y = (const int*)d_in[1];
    float* out = (float*)d_out;
    (void)in_sizes; (void)n_in; (void)out_size;

    cudaFuncSetAttribute(classA_kernel, cudaFuncAttributeMaxDynamicSharedMemorySize, GSMEM);
    cudaFuncSetAttribute(gemmB_kernel,  cudaFuncAttributeMaxDynamicSharedMemorySize, GSMEMB);

    prep_kernel<<<NPTS / 8, 256>>>(X);
    perm_kernel<<<1, 1024>>>(y);
    classA_kernel<<<NCLS * CTRI, 256, GSMEM>>>();
    anchor_kernel<<<NPTS / 128, 128>>>();
    gemmB_kernel<<<NTRI, 256, GSMEMB>>>();
    fixup_kernel<<<512, 256>>>();
    fin_part_kernel<<<64, 128>>>();
    fin2_kernel<<<1, 256>>>(y, out);
}